// round 9
// baseline (speedup 1.0000x reference)
#include <cuda_runtime.h>

#define NT 256

__device__ double       g_acc;
__device__ unsigned int g_cnt;

__device__ __forceinline__ float frcp(float x) {
    float r; asm("rcp.approx.f32 %0, %1;" : "=f"(r) : "f"(x)); return r;
}
__device__ __forceinline__ float clampf(float x, float lo, float hi) {
    return fminf(fmaxf(x, lo), hi);
}

struct Chain { float acc, px, py, fx, fy; };

__device__ __forceinline__ void edge2(float cx, float cy, float nx, float ny,
                                      float lo2, float hi2, Chain& s, bool first) {
    float rx = nx - cx, ry = ny - cy;
    float inv = frcp(ry);
    float tl = (lo2 - cy) * inv, th = (hi2 - cy) * inv;
    float ta = fminf(tl, th), tb = fmaxf(tl, th);
    float t0 = clampf(ta, 0.0f, 1.0f);
    float t1 = clampf(tb, 0.0f, 1.0f);
    float e0x = fmaf(t0, rx, cx);
    float e0y = clampf(fmaf(t0, ry, cy), lo2, hi2);
    float e1x = fmaf(t1, rx, cx);
    float e1y = clampf(fmaf(t1, ry, cy), lo2, hi2);
    if (first) { s.fx = e0x; s.fy = e0y; }
    else       { s.acc += fmaf(s.px, e0y, -(s.py * e0x)); }
    s.acc += fmaf(e0x, e1y, -(e0y * e1x));
    s.px = e1x; s.py = e1y;
}

__device__ __forceinline__ float pair_loss(const float* __restrict__ p,
                                           const float* __restrict__ q) {
    float x1 = p[0], y1 = p[1], hw1 = 0.5f * p[2], hh1 = 0.5f * p[3], a1 = p[4];
    float x2 = q[0], y2 = q[1], hw2 = 0.5f * q[2], hh2 = 0.5f * q[3], a2 = q[4];

    // Box2's local frame: clip region is the axis box [±hw2]x[±hh2].
    float sf, cf, s2, c2;
    __sincosf(a1 - a2, &sf, &cf);
    __sincosf(a2, &s2, &c2);
    float ddx = x1 - x2, ddy = y1 - y2;
    float dx = fmaf(ddx, c2, ddy * s2);
    float dy = fmaf(-ddx, s2, ddy * c2);

    float ux = hw1 * cf, uy = hw1 * sf;
    float vx = -hh1 * sf, vy = hh1 * cf;
    float Px[4], Py[4];
    Px[0] = dx - ux - vx; Py[0] = dy - uy - vy;
    Px[1] = dx + ux - vx; Py[1] = dy + uy - vy;
    Px[2] = dx + ux + vx; Py[2] = dy + uy + vy;
    Px[3] = dx - ux + vx; Py[3] = dy - uy + vy;

    const float lo = -hw2, hi = hw2;
    const float lo2 = -hh2, hi2 = hh2;

    Chain st; st.acc = 0.0f; st.px = st.py = st.fx = st.fy = 0.0f;
    float F8x = 0.0f, F8y = 0.0f, p8x = 0.0f, p8y = 0.0f;

    #pragma unroll
    for (int k = 0; k < 4; k++) {
        int kn = (k + 1) & 3;
        float cx = Px[k], cy = Py[k];
        float rx = Px[kn] - cx, ry = Py[kn] - cy;
        float inv = frcp(rx);
        float tl = (lo - cx) * inv, th = (hi - cx) * inv;
        float ta = fminf(tl, th), tb = fmaxf(tl, th);
        float t0 = clampf(ta, 0.0f, 1.0f);
        float t1 = clampf(tb, 0.0f, 1.0f);
        float v0x = clampf(fmaf(t0, rx, cx), lo, hi);
        float v0y = fmaf(t0, ry, cy);
        float v1x = clampf(fmaf(t1, rx, cx), lo, hi);
        float v1y = fmaf(t1, ry, cy);
        if (k == 0) {
            F8x = v0x; F8y = v0y;
            edge2(v0x, v0y, v1x, v1y, lo2, hi2, st, true);
        } else {
            edge2(p8x, p8y, v0x, v0y, lo2, hi2, st, false);
            edge2(v0x, v0y, v1x, v1y, lo2, hi2, st, false);
        }
        p8x = v1x; p8y = v1y;
    }
    edge2(p8x, p8y, F8x, F8y, lo2, hi2, st, false);
    st.acc += fmaf(st.px, st.fy, -(st.py * st.fx));

    float area = 0.5f * fabsf(st.acc);
    float A1 = 4.0f * hw1 * hh1, A2 = 4.0f * hw2 * hh2;
    float iou = area / fmaxf(A1 + A2 - area, 1e-10f);
    return -__logf(fmaxf(iou, 1e-6f));
}

__global__ void __launch_bounds__(NT, 3)
k_loss(const float* __restrict__ pred, const float* __restrict__ tgt,
       float* __restrict__ out, int n, int nblocks) {
    __shared__ double ssum[NT / 32];

    const int tid  = threadIdx.x;
    const int base = blockIdx.x * (2 * NT) + tid;

    // Two independent pairs per thread -> ILP hides MUFU/FMA/LDG latency.
    float loss = 0.0f;
    int i0 = base, i1 = base + NT;
    float l0 = 0.0f, l1 = 0.0f;
    if (i0 < n) l0 = pair_loss(pred + (size_t)i0 * 5, tgt + (size_t)i0 * 5);
    if (i1 < n) l1 = pair_loss(pred + (size_t)i1 * 5, tgt + (size_t)i1 * 5);
    loss = l0 + l1;

    // ---- block reduction ----
    #pragma unroll
    for (int o = 16; o > 0; o >>= 1)
        loss += __shfl_down_sync(0xFFFFFFFFu, loss, o);
    int lane = tid & 31, warp = tid >> 5;
    if (lane == 0) ssum[warp] = (double)loss;
    __syncthreads();

    if (tid == 0) {
        double t = 0.0;
        #pragma unroll
        for (int w = 0; w < NT / 32; w++) t += ssum[w];
        atomicAdd(&g_acc, t);
        __threadfence();
        unsigned int done = atomicAdd(&g_cnt, 1u);
        if (done == (unsigned int)(nblocks - 1)) {
            double a = atomicAdd(&g_acc, 0.0);
            out[0] = (float)(a / (double)n);
            atomicExch((unsigned long long*)&g_acc, 0ull);
            atomicExch(&g_cnt, 0u);
        }
    }
}

extern "C" void kernel_launch(void* const* d_in, const int* in_sizes, int n_in,
                              void* d_out, int out_size) {
    const float* pred = (const float*)d_in[0];
    const float* tgt  = (const float*)d_in[1];
    int n = in_sizes[0] / 5;
    int nblocks = (n + 2 * NT - 1) / (2 * NT);
    k_loss<<<nblocks, NT>>>(pred, tgt, (float*)d_out, n, nblocks);
}

// round 10
// speedup vs baseline: 1.0791x; 1.0791x over previous
#include <cuda_runtime.h>

#define NT 256

__device__ double       g_acc;
__device__ unsigned int g_cnt;

__device__ __forceinline__ float frcp(float x) {
    float r; asm("rcp.approx.f32 %0, %1;" : "=f"(r) : "f"(x)); return r;
}

__global__ void __launch_bounds__(NT)
k_loss(const float* __restrict__ pred, const float* __restrict__ tgt,
       float* __restrict__ out, int n, int nblocks) {
    __shared__ double ssum[NT / 32];

    const int tid = threadIdx.x;
    const int i   = blockIdx.x * NT + tid;

    float loss = 0.0f;
    if (i < n) {
        const float* p = pred + (size_t)i * 5;
        const float* q = tgt  + (size_t)i * 5;
        float x1 = p[0], y1 = p[1], w1 = p[2], h1 = p[3], a1 = p[4];
        float x2 = q[0], y2 = q[1], w2 = q[2], h2 = q[3], a2 = q[4];

        // Box2 local frame, then affine-normalize so the clip box is [0,1]^2.
        float sf, cf, s2, c2;
        __sincosf(a1 - a2, &sf, &cf);
        __sincosf(a2, &s2, &c2);
        float ddx = x1 - x2, ddy = y1 - y2;
        float dxl = fmaf(ddx, c2, ddy * s2);
        float dyl = fmaf(-ddx, s2, ddy * c2);

        float iw = frcp(w2), ih = frcp(h2);
        float du = fmaf(dxl, iw, 0.5f);          // normalized center of box1
        float dv = fmaf(dyl, ih, 0.5f);
        float hw1 = 0.5f * w1, hh1 = 0.5f * h1;
        float uxn = (hw1 * cf) * iw, uyn = (hw1 * sf) * ih;
        float vxn = -(hh1 * sf) * iw, vyn = (hh1 * cf) * ih;

        float Pu[4], Pv[4];
        Pu[0] = du - uxn - vxn; Pv[0] = dv - uyn - vyn;
        Pu[1] = du + uxn - vxn; Pv[1] = dv + uyn - vyn;
        Pu[2] = du + uxn + vxn; Pv[2] = dv + uyn + vyn;
        Pu[3] = du - uxn + vxn; Pv[3] = dv - uyn + vyn;

        // Streaming pass-2 state (v-clip to [0,1] + shoelace chain).
        float acc = 0.0f, pxc = 0.0f, pyc = 0.0f, fxc = 0.0f, fyc = 0.0f;
        float F8u = 0.0f, F8v = 0.0f, p8u = 0.0f, p8v = 0.0f;

        // edge2 as a lambda-like macro body: clip edge (cu,cv)->(nu,nv) against
        // v in [0,1], emit 2 points unconditionally, fold into shoelace.
        #define EDGE2(cu_, cv_, nu_, nv_, FIRST)                               \
        {                                                                      \
            float ru = (nu_) - (cu_), rv = (nv_) - (cv_);                      \
            float inv = frcp(rv);                                              \
            float tl = __saturatef(-(cv_) * inv);                              \
            float th = __saturatef(fmaf(-(cv_), inv, inv));                    \
            float t0 = fminf(tl, th), t1 = fmaxf(tl, th);                      \
            float e0u = fmaf(t0, ru, (cu_));                                   \
            float e0v = __saturatef(fmaf(t0, rv, (cv_)));                      \
            float e1u = fmaf(t1, ru, (cu_));                                   \
            float e1v = __saturatef(fmaf(t1, rv, (cv_)));                      \
            if (FIRST) { fxc = e0u; fyc = e0v; }                               \
            else { acc = fmaf(pxc, e0v, acc); acc = fmaf(-pyc, e0u, acc); }    \
            acc = fmaf(e0u, e1v, acc);                                         \
            acc = fmaf(-e0v, e1u, acc);                                        \
            pxc = e1u; pyc = e1v;                                              \
        }

        // Pass 1: u-clip each quad edge to [0,1]; stream emissions into pass 2.
        #pragma unroll
        for (int k = 0; k < 4; k++) {
            int kn = (k + 1) & 3;
            float cu = Pu[k], cv = Pv[k];
            float ru = Pu[kn] - cu, rv = Pv[kn] - cv;
            float inv = frcp(ru);
            float tl = __saturatef(-cu * inv);
            float th = __saturatef(fmaf(-cu, inv, inv));
            float t0 = fminf(tl, th), t1 = fmaxf(tl, th);
            float v0u = __saturatef(fmaf(t0, ru, cu));
            float v0v = fmaf(t0, rv, cv);
            float v1u = __saturatef(fmaf(t1, ru, cu));
            float v1v = fmaf(t1, rv, cv);
            if (k == 0) {
                F8u = v0u; F8v = v0v;
                EDGE2(v0u, v0v, v1u, v1v, true);
            } else {
                EDGE2(p8u, p8v, v0u, v0v, false);
                EDGE2(v0u, v0v, v1u, v1v, false);
            }
            p8u = v1u; p8v = v1v;
        }
        EDGE2(p8u, p8v, F8u, F8v, false);            // close the 8-gon
        acc = fmaf(pxc, fyc, acc);                   // close the 16-gon
        acc = fmaf(-pyc, fxc, acc);
        #undef EDGE2

        float area = 0.5f * fabsf(acc) * (w2 * h2);  // un-normalize
        float A1 = w1 * h1, A2 = w2 * h2;
        float iou = area / fmaxf(A1 + A2 - area, 1e-10f);
        loss = -__logf(fmaxf(iou, 1e-6f));
    }

    // ---- block reduction ----
    #pragma unroll
    for (int o = 16; o > 0; o >>= 1)
        loss += __shfl_down_sync(0xFFFFFFFFu, loss, o);
    int lane = tid & 31, warp = tid >> 5;
    if (lane == 0) ssum[warp] = (double)loss;
    __syncthreads();

    if (tid == 0) {
        double t = 0.0;
        #pragma unroll
        for (int w = 0; w < NT / 32; w++) t += ssum[w];
        atomicAdd(&g_acc, t);
        __threadfence();
        unsigned int done = atomicAdd(&g_cnt, 1u);
        if (done == (unsigned int)(nblocks - 1)) {
            double a = atomicAdd(&g_acc, 0.0);
            out[0] = (float)(a / (double)n);
            atomicExch((unsigned long long*)&g_acc, 0ull);
            atomicExch(&g_cnt, 0u);
        }
    }
}

extern "C" void kernel_launch(void* const* d_in, const int* in_sizes, int n_in,
                              void* d_out, int out_size) {
    const float* pred = (const float*)d_in[0];
    const float* tgt  = (const float*)d_in[1];
    int n = in_sizes[0] / 5;
    int nblocks = (n + NT - 1) / NT;
    k_loss<<<nblocks, NT>>>(pred, tgt, (float*)d_out, n, nblocks);
}